// round 1
// baseline (speedup 1.0000x reference)
#include <cuda_runtime.h>
#include <math.h>

#define NB 16
#define D_NEED 29      // frames d = 31..59
#define D_OFF 31
#define T_NEED 15      // t = 45..59

// scratch (no allocations allowed)
__device__ float g_s1[NB * D_NEED * 2500];     // spatial-conv output, 50x50 per (b,d)
__device__ float g_flat[NB * T_NEED * 100];    // last-conv output, 100 per (b,t)

// ---------------------------------------------------------------------------
// Kernel A: 5x5 stride-5 spatial conv on frames 31..59 only.
// grid = (10 row-bands, 29 frames, 16 batches), block = 256.
// Each block: 5 output rows = 25 input rows x 250 cols (25 KB smem).
// ---------------------------------------------------------------------------
__global__ void __launch_bounds__(256) kA(const float* __restrict__ x,
                                          const float* __restrict__ sw)
{
    __shared__ float sm[6250];   // 25 rows * 250 cols
    __shared__ float w[25];
    const int g    = blockIdx.x;   // 0..9 (5 output rows each)
    const int dIdx = blockIdx.y;   // 0..28
    const int b    = blockIdx.z;   // 0..15
    const int tid  = threadIdx.x;

    if (tid < 25) w[tid] = sw[tid];

    // band base: frame (b,31+dIdx), input rows g*25 .. g*25+24
    const float* src = x + ((size_t)(b * 60 + (D_OFF + dIdx))) * 62500u
                         + (size_t)g * 6250u;
    // 6250 floats = 3125 float2, band byte offset 25000 -> 8B aligned
    const float2* s2 = (const float2*)src;
    float2* d2 = (float2*)sm;
    #pragma unroll 4
    for (int i = tid; i < 3125; i += 256) d2[i] = s2[i];
    __syncthreads();

    if (tid < 250) {
        const int orow = tid / 50;     // 0..4
        const int ocol = tid % 50;
        const float* p = sm + orow * 5 * 250 + ocol * 5;
        float acc = 0.f;
        #pragma unroll
        for (int i = 0; i < 5; i++)
            #pragma unroll
            for (int j = 0; j < 5; j++)
                acc = fmaf(w[i * 5 + j], p[i * 250 + j], acc);
        g_s1[(b * D_NEED + dIdx) * 2500 + g * 250 + tid] = acc;
    }
}

// ---------------------------------------------------------------------------
// Kernel B: temporal 15-tap conv + ReLU, then 5x5 stride-5 "last" conv.
// grid = (15 timesteps, 16 batches), block = 256.
// first[b,t,pix] = relu(sum_k tw[k] * s1[b, (t-45)+k, pix])
// flat[b,t,m]    = sum_{i,j} lw[i,j] * first[5h+i, 5w+j]
// ---------------------------------------------------------------------------
__global__ void __launch_bounds__(256) kB(const float* __restrict__ tw_g,
                                          const float* __restrict__ lw_g)
{
    __shared__ float first[2500];
    __shared__ float tw[15];
    __shared__ float lw[25];
    const int tRel = blockIdx.x;   // t = 45 + tRel
    const int b    = blockIdx.y;
    const int tid  = threadIdx.x;

    if (tid < 15) tw[tid] = tw_g[tid];
    if (tid >= 32 && tid < 57) lw[tid - 32] = lw_g[tid - 32];
    __syncthreads();

    // frame base: dIdx = tRel + k, k = 0..14  (d = t-14+k, all in [31,59])
    const float4* b4 = (const float4*)(g_s1 + (b * D_NEED + tRel) * 2500);
    float4* f4 = (float4*)first;
    for (int i = tid; i < 625; i += 256) {
        float4 acc = make_float4(0.f, 0.f, 0.f, 0.f);
        #pragma unroll
        for (int k = 0; k < 15; k++) {
            float4 v = b4[k * 625 + i];
            float c = tw[k];
            acc.x = fmaf(c, v.x, acc.x);
            acc.y = fmaf(c, v.y, acc.y);
            acc.z = fmaf(c, v.z, acc.z);
            acc.w = fmaf(c, v.w, acc.w);
        }
        acc.x = fmaxf(acc.x, 0.f);
        acc.y = fmaxf(acc.y, 0.f);
        acc.z = fmaxf(acc.z, 0.f);
        acc.w = fmaxf(acc.w, 0.f);
        f4[i] = acc;
    }
    __syncthreads();

    if (tid < 100) {
        const int h = tid / 10, wv = tid % 10;
        const float* p = first + h * 5 * 50 + wv * 5;
        float acc = 0.f;
        #pragma unroll
        for (int i = 0; i < 5; i++)
            #pragma unroll
            for (int j = 0; j < 5; j++)
                acc = fmaf(lw[i * 5 + j], p[i * 50 + j], acc);
        g_flat[(b * T_NEED + tRel) * 100 + tid] = acc;
    }
}

// ---------------------------------------------------------------------------
// Kernel C: ama/gang cone at t=59 + 49-tap dot product. grid = 16, block = 64.
// ama_pre[t,j]  = ac * flat[t, 2j]
// gang_pre[t,j] = gc * flat[t, (2j+25)%100]
// ama_out  = alpha * sigmoid(sum_k akw[k]*ama_pre[45+k,j] + akb)
// gang_out =          sum_k gkw[k]*gang_pre[45+k,j] + gkb
// out[b]   = sum_j gcol[j] * sigmoid(gang_out - |ama_out|)
// ---------------------------------------------------------------------------
__global__ void __launch_bounds__(64) kC(const float* __restrict__ acw,
                                         const float* __restrict__ akw,
                                         const float* __restrict__ akb,
                                         const float* __restrict__ alw,
                                         const float* __restrict__ gcw,
                                         const float* __restrict__ gkw,
                                         const float* __restrict__ gkb,
                                         const float* __restrict__ gcolw,
                                         float* __restrict__ out)
{
    __shared__ float fl[T_NEED * 100];
    __shared__ float red[49];
    const int b   = blockIdx.x;
    const int tid = threadIdx.x;

    for (int i = tid; i < T_NEED * 100; i += 64)
        fl[i] = g_flat[b * (T_NEED * 100) + i];
    __syncthreads();

    if (tid < 49) {
        const float ac = acw[0], al = alw[0], gc = gcw[0];
        const int ja = 2 * tid;
        const int jg = (2 * tid + 25) % 100;
        float a = akb[0];
        float g = gkb[0];
        #pragma unroll
        for (int k = 0; k < 15; k++) {
            a = fmaf(akw[k], ac * fl[k * 100 + ja], a);
            g = fmaf(gkw[k], gc * fl[k * 100 + jg], g);
        }
        const float amo = al / (1.f + expf(-a));
        const float val = 1.f / (1.f + expf(-(g - fabsf(amo))));
        red[tid] = gcolw[tid] * val;
    }
    __syncthreads();

    if (tid == 0) {
        float s = 0.f;
        #pragma unroll
        for (int j = 0; j < 49; j++) s += red[j];
        out[b] = s;
    }
}

// ---------------------------------------------------------------------------
extern "C" void kernel_launch(void* const* d_in, const int* in_sizes, int n_in,
                              void* d_out, int out_size)
{
    const float* x          = (const float*)d_in[0];
    const float* space_w    = (const float*)d_in[1];
    const float* temporal_w = (const float*)d_in[2];
    const float* last_w     = (const float*)d_in[3];
    const float* ama_create = (const float*)d_in[4];
    const float* ama_kern   = (const float*)d_in[5];
    const float* ama_kern_b = (const float*)d_in[6];
    const float* ama_alpha  = (const float*)d_in[7];
    const float* gang_create= (const float*)d_in[8];
    const float* gang_kern  = (const float*)d_in[9];
    const float* gang_kern_b= (const float*)d_in[10];
    const float* gang_col   = (const float*)d_in[11];
    float* out = (float*)d_out;

    dim3 gA(10, D_NEED, NB);
    kA<<<gA, 256>>>(x, space_w);

    dim3 gB(T_NEED, NB);
    kB<<<gB, 256>>>(temporal_w, last_w);

    kC<<<NB, 64>>>(ama_create, ama_kern, ama_kern_b, ama_alpha,
                   gang_create, gang_kern, gang_kern_b, gang_col, out);
}

// round 2
// speedup vs baseline: 1.0471x; 1.0471x over previous
#include <cuda_runtime.h>
#include <math.h>

#define NB 16
#define D_NEED 29      // frames d = 31..59
#define D_OFF 31
#define T_NEED 15      // t = 45..59

// scratch (no allocations allowed)
__device__ float g_s1[NB * D_NEED * 2500];     // spatial-conv output, 50x50 per (b,d)
__device__ float g_flat[NB * T_NEED * 100];    // last-conv output, 100 per (b,t)

// ---------------------------------------------------------------------------
// Kernel A: 5x5 stride-5 spatial conv on frames 31..59 only.
// grid = (5 double-bands, 29 frames, 16 batches), block = 512.
// Each block: 10 output rows = 50 input rows x 250 cols (50 KB smem, float4).
// ---------------------------------------------------------------------------
__global__ void __launch_bounds__(512) kA(const float* __restrict__ x,
                                          const float* __restrict__ sw)
{
    __shared__ float sm[12500];   // 50 rows * 250 cols
    __shared__ float w[25];
    const int g2   = blockIdx.x;   // 0..4 (10 output rows each)
    const int dIdx = blockIdx.y;   // 0..28
    const int b    = blockIdx.z;   // 0..15
    const int tid  = threadIdx.x;

    if (tid < 25) w[tid] = sw[tid];

    // double-band base: frame (b, 31+dIdx), input rows g2*50 .. g2*50+49
    // byte offset = frame*250000 + g2*50000  -> 16B aligned
    const float4* s4 = (const float4*)(x + ((size_t)(b * 60 + (D_OFF + dIdx))) * 62500u
                                         + (size_t)g2 * 12500u);
    float4* d4 = (float4*)sm;
    // 12500 floats = 3125 float4; 512 threads -> 6.1 iters, MLP-rich
    #pragma unroll 7
    for (int i = tid; i < 3125; i += 512) d4[i] = __ldcs(s4 + i);
    __syncthreads();

    // 500 outputs (10 rows x 50 cols)
    if (tid < 500) {
        const int orow = tid / 50;     // 0..9
        const int ocol = tid % 50;
        const float* p = sm + orow * 5 * 250 + ocol * 5;
        float acc = 0.f;
        #pragma unroll
        for (int i = 0; i < 5; i++)
            #pragma unroll
            for (int j = 0; j < 5; j++)
                acc = fmaf(w[i * 5 + j], p[i * 250 + j], acc);
        g_s1[(b * D_NEED + dIdx) * 2500 + g2 * 500 + tid] = acc;
    }
}

// ---------------------------------------------------------------------------
// Kernel B: temporal 15-tap conv + ReLU, then 5x5 stride-5 "last" conv.
// grid = (15 timesteps, 16 batches), block = 256.
// ---------------------------------------------------------------------------
__global__ void __launch_bounds__(256) kB(const float* __restrict__ tw_g,
                                          const float* __restrict__ lw_g)
{
    __shared__ float first[2500];
    __shared__ float tw[15];
    __shared__ float lw[25];
    const int tRel = blockIdx.x;   // t = 45 + tRel
    const int b    = blockIdx.y;
    const int tid  = threadIdx.x;

    if (tid < 15) tw[tid] = tw_g[tid];
    if (tid >= 32 && tid < 57) lw[tid - 32] = lw_g[tid - 32];
    __syncthreads();

    // frame base: dIdx = tRel + k, k = 0..14  (d = t-14+k, all in [31,59])
    const float4* b4 = (const float4*)(g_s1 + (b * D_NEED + tRel) * 2500);
    float4* f4 = (float4*)first;
    for (int i = tid; i < 625; i += 256) {
        float4 acc = make_float4(0.f, 0.f, 0.f, 0.f);
        #pragma unroll
        for (int k = 0; k < 15; k++) {
            float4 v = b4[k * 625 + i];
            float c = tw[k];
            acc.x = fmaf(c, v.x, acc.x);
            acc.y = fmaf(c, v.y, acc.y);
            acc.z = fmaf(c, v.z, acc.z);
            acc.w = fmaf(c, v.w, acc.w);
        }
        acc.x = fmaxf(acc.x, 0.f);
        acc.y = fmaxf(acc.y, 0.f);
        acc.z = fmaxf(acc.z, 0.f);
        acc.w = fmaxf(acc.w, 0.f);
        f4[i] = acc;
    }
    __syncthreads();

    if (tid < 100) {
        const int h = tid / 10, wv = tid % 10;
        const float* p = first + h * 5 * 50 + wv * 5;
        float acc = 0.f;
        #pragma unroll
        for (int i = 0; i < 5; i++)
            #pragma unroll
            for (int j = 0; j < 5; j++)
                acc = fmaf(lw[i * 5 + j], p[i * 50 + j], acc);
        g_flat[(b * T_NEED + tRel) * 100 + tid] = acc;
    }
}

// ---------------------------------------------------------------------------
// Kernel C: ama/gang cone at t=59 + 49-tap dot product. grid = 16, block = 64.
// ---------------------------------------------------------------------------
__global__ void __launch_bounds__(64) kC(const float* __restrict__ acw,
                                         const float* __restrict__ akw,
                                         const float* __restrict__ akb,
                                         const float* __restrict__ alw,
                                         const float* __restrict__ gcw,
                                         const float* __restrict__ gkw,
                                         const float* __restrict__ gkb,
                                         const float* __restrict__ gcolw,
                                         float* __restrict__ out)
{
    __shared__ float fl[T_NEED * 100];
    __shared__ float red[49];
    const int b   = blockIdx.x;
    const int tid = threadIdx.x;

    for (int i = tid; i < T_NEED * 100; i += 64)
        fl[i] = g_flat[b * (T_NEED * 100) + i];
    __syncthreads();

    if (tid < 49) {
        const float ac = acw[0], al = alw[0], gc = gcw[0];
        const int ja = 2 * tid;
        const int jg = (2 * tid + 25) % 100;
        float a = akb[0];
        float g = gkb[0];
        #pragma unroll
        for (int k = 0; k < 15; k++) {
            a = fmaf(akw[k], ac * fl[k * 100 + ja], a);
            g = fmaf(gkw[k], gc * fl[k * 100 + jg], g);
        }
        const float amo = al / (1.f + expf(-a));
        const float val = 1.f / (1.f + expf(-(g - fabsf(amo))));
        red[tid] = gcolw[tid] * val;
    }
    __syncthreads();

    if (tid == 0) {
        float s = 0.f;
        #pragma unroll
        for (int j = 0; j < 49; j++) s += red[j];
        out[b] = s;
    }
}

// ---------------------------------------------------------------------------
extern "C" void kernel_launch(void* const* d_in, const int* in_sizes, int n_in,
                              void* d_out, int out_size)
{
    const float* x          = (const float*)d_in[0];
    const float* space_w    = (const float*)d_in[1];
    const float* temporal_w = (const float*)d_in[2];
    const float* last_w     = (const float*)d_in[3];
    const float* ama_create = (const float*)d_in[4];
    const float* ama_kern   = (const float*)d_in[5];
    const float* ama_kern_b = (const float*)d_in[6];
    const float* ama_alpha  = (const float*)d_in[7];
    const float* gang_create= (const float*)d_in[8];
    const float* gang_kern  = (const float*)d_in[9];
    const float* gang_kern_b= (const float*)d_in[10];
    const float* gang_col   = (const float*)d_in[11];
    float* out = (float*)d_out;

    dim3 gA(5, D_NEED, NB);
    kA<<<gA, 512>>>(x, space_w);

    dim3 gB(T_NEED, NB);
    kB<<<gB, 256>>>(temporal_w, last_w);

    kC<<<NB, 64>>>(ama_create, ama_kern, ama_kern_b, ama_alpha,
                   gang_create, gang_kern, gang_kern_b, gang_col, out);
}

// round 3
// speedup vs baseline: 1.2910x; 1.2330x over previous
#include <cuda_runtime.h>
#include <math.h>
#include <stdint.h>

#define NB 16
#define D_NEED 29      // frames d = 31..59
#define D_OFF 31
#define T_NEED 15      // t = 45..59

#define BANDS 2320          // NB * D_NEED * 5 double-bands
#define GRID_A 296          // 2 blocks per SM on 148 SMs
#define BAND_FLOATS 12500   // 50 rows * 250 cols
#define BAND_BYTES 50000

// scratch (no allocations allowed)
__device__ float g_s1[NB * D_NEED * 2500];     // spatial-conv output, 50x50 per (b,d)
__device__ float g_flat[NB * T_NEED * 100];    // last-conv output, 100 per (b,t)

__device__ __forceinline__ unsigned su32(const void* p) {
    return (unsigned)__cvta_generic_to_shared(p);
}

__device__ __forceinline__ void mbar_wait(unsigned mbar, unsigned phase) {
    unsigned done = 0;
    do {
        asm volatile(
            "{\n\t.reg .pred p;\n\t"
            "mbarrier.try_wait.parity.shared.b64 p, [%1], %2, 10000000;\n\t"
            "selp.b32 %0, 1, 0, p;\n\t}"
            : "=r"(done) : "r"(mbar), "r"(phase) : "memory");
    } while (!done);
}

// ---------------------------------------------------------------------------
// Kernel A: 5x5 stride-5 spatial conv on frames 31..59, TMA double-buffered.
// grid = 296 persistent-ish blocks, block = 512, dyn smem = 100 KB.
// Each block walks bands id = blockIdx.x + j*296 (j = 0..~7).
// Band id -> (b = id/145, dIdx = (id%145)/5, g2 = id%5): 10 output rows.
// ---------------------------------------------------------------------------
__global__ void __launch_bounds__(512) kA(const float* __restrict__ x,
                                          const float* __restrict__ sw)
{
    extern __shared__ float dbuf[];                 // 2 * 12500 floats
    __shared__ unsigned long long mbar[2];
    __shared__ float w[25];
    const int tid = threadIdx.x;

    const unsigned mb0 = su32(&mbar[0]);
    const unsigned mb1 = su32(&mbar[1]);
    const unsigned bb0 = su32(dbuf);
    const unsigned bb1 = su32(dbuf + BAND_FLOATS);

    if (tid == 0) {
        asm volatile("mbarrier.init.shared.b64 [%0], 1;" :: "r"(mb0) : "memory");
        asm volatile("mbarrier.init.shared.b64 [%0], 1;" :: "r"(mb1) : "memory");
        asm volatile("fence.proxy.async.shared::cta;" ::: "memory");
    }
    if (tid < 25) w[tid] = sw[tid];
    __syncthreads();

    const int nMine = (BANDS - 1 - (int)blockIdx.x) / GRID_A + 1;

    auto issueTMA = [&](int j) {
        const int id  = blockIdx.x + j * GRID_A;
        const int b   = id / 145;
        const int rem = id % 145;
        const float* src = x + (size_t)(b * 60 + D_OFF + rem / 5) * 62500u
                             + (size_t)(rem % 5) * BAND_FLOATS;
        const unsigned mb = (j & 1) ? mb1 : mb0;
        const unsigned bb = (j & 1) ? bb1 : bb0;
        asm volatile("mbarrier.arrive.expect_tx.shared.b64 _, [%0], %1;"
                     :: "r"(mb), "n"(BAND_BYTES) : "memory");
        asm volatile("cp.async.bulk.shared::cta.global.mbarrier::complete_tx::bytes "
                     "[%0], [%1], %2, [%3];"
                     :: "r"(bb), "l"(src), "n"(BAND_BYTES), "r"(mb) : "memory");
    };

    if (tid == 0) {
        issueTMA(0);
        if (nMine > 1) issueTMA(1);
    }

    for (int j = 0; j < nMine; j++) {
        const int bu = j & 1;
        mbar_wait(bu ? mb1 : mb0, (j >> 1) & 1);

        const int id = blockIdx.x + j * GRID_A;
        if (tid < 500) {
            const float* p = dbuf + bu * BAND_FLOATS
                           + (tid / 50) * 1250 + (tid % 50) * 5;
            float acc = 0.f;
            #pragma unroll
            for (int i = 0; i < 5; i++)
                #pragma unroll
                for (int jj = 0; jj < 5; jj++)
                    acc = fmaf(w[i * 5 + jj], p[i * 250 + jj], acc);
            g_s1[id * 500 + tid] = acc;
        }
        __syncthreads();                 // all reads of buf[bu] done
        if (tid == 0 && j + 2 < nMine) issueTMA(j + 2);
    }
}

// ---------------------------------------------------------------------------
// Kernel B: temporal 15-tap conv + ReLU, then 5x5 stride-5 "last" conv.
// grid = (15 timesteps, 16 batches), block = 256.
// ---------------------------------------------------------------------------
__global__ void __launch_bounds__(256) kB(const float* __restrict__ tw_g,
                                          const float* __restrict__ lw_g)
{
    __shared__ float first[2500];
    __shared__ float tw[15];
    __shared__ float lw[25];
    const int tRel = blockIdx.x;   // t = 45 + tRel
    const int b    = blockIdx.y;
    const int tid  = threadIdx.x;

    if (tid < 15) tw[tid] = tw_g[tid];
    if (tid >= 32 && tid < 57) lw[tid - 32] = lw_g[tid - 32];
    __syncthreads();

    const float4* b4 = (const float4*)(g_s1 + (b * D_NEED + tRel) * 2500);
    float4* f4 = (float4*)first;
    for (int i = tid; i < 625; i += 256) {
        float4 acc = make_float4(0.f, 0.f, 0.f, 0.f);
        #pragma unroll
        for (int k = 0; k < 15; k++) {
            float4 v = b4[k * 625 + i];
            float c = tw[k];
            acc.x = fmaf(c, v.x, acc.x);
            acc.y = fmaf(c, v.y, acc.y);
            acc.z = fmaf(c, v.z, acc.z);
            acc.w = fmaf(c, v.w, acc.w);
        }
        acc.x = fmaxf(acc.x, 0.f);
        acc.y = fmaxf(acc.y, 0.f);
        acc.z = fmaxf(acc.z, 0.f);
        acc.w = fmaxf(acc.w, 0.f);
        f4[i] = acc;
    }
    __syncthreads();

    if (tid < 100) {
        const int h = tid / 10, wv = tid % 10;
        const float* p = first + h * 5 * 50 + wv * 5;
        float acc = 0.f;
        #pragma unroll
        for (int i = 0; i < 5; i++)
            #pragma unroll
            for (int j = 0; j < 5; j++)
                acc = fmaf(lw[i * 5 + j], p[i * 50 + j], acc);
        g_flat[(b * T_NEED + tRel) * 100 + tid] = acc;
    }
}

// ---------------------------------------------------------------------------
// Kernel C: ama/gang cone at t=59 + 49-tap dot product. grid = 16, block = 64.
// ---------------------------------------------------------------------------
__global__ void __launch_bounds__(64) kC(const float* __restrict__ acw,
                                         const float* __restrict__ akw,
                                         const float* __restrict__ akb,
                                         const float* __restrict__ alw,
                                         const float* __restrict__ gcw,
                                         const float* __restrict__ gkw,
                                         const float* __restrict__ gkb,
                                         const float* __restrict__ gcolw,
                                         float* __restrict__ out)
{
    __shared__ float fl[T_NEED * 100];
    __shared__ float red[49];
    const int b   = blockIdx.x;
    const int tid = threadIdx.x;

    for (int i = tid; i < T_NEED * 100; i += 64)
        fl[i] = g_flat[b * (T_NEED * 100) + i];
    __syncthreads();

    if (tid < 49) {
        const float ac = acw[0], al = alw[0], gc = gcw[0];
        const int ja = 2 * tid;
        const int jg = (2 * tid + 25) % 100;
        float a = akb[0];
        float g = gkb[0];
        #pragma unroll
        for (int k = 0; k < 15; k++) {
            a = fmaf(akw[k], ac * fl[k * 100 + ja], a);
            g = fmaf(gkw[k], gc * fl[k * 100 + jg], g);
        }
        const float amo = al / (1.f + expf(-a));
        const float val = 1.f / (1.f + expf(-(g - fabsf(amo))));
        red[tid] = gcolw[tid] * val;
    }
    __syncthreads();

    if (tid == 0) {
        float s = 0.f;
        #pragma unroll
        for (int j = 0; j < 49; j++) s += red[j];
        out[b] = s;
    }
}

// ---------------------------------------------------------------------------
extern "C" void kernel_launch(void* const* d_in, const int* in_sizes, int n_in,
                              void* d_out, int out_size)
{
    const float* x          = (const float*)d_in[0];
    const float* space_w    = (const float*)d_in[1];
    const float* temporal_w = (const float*)d_in[2];
    const float* last_w     = (const float*)d_in[3];
    const float* ama_create = (const float*)d_in[4];
    const float* ama_kern   = (const float*)d_in[5];
    const float* ama_kern_b = (const float*)d_in[6];
    const float* ama_alpha  = (const float*)d_in[7];
    const float* gang_create= (const float*)d_in[8];
    const float* gang_kern  = (const float*)d_in[9];
    const float* gang_kern_b= (const float*)d_in[10];
    const float* gang_col   = (const float*)d_in[11];
    float* out = (float*)d_out;

    const int dynA = 2 * BAND_BYTES;   // 100000 bytes
    cudaFuncSetAttribute(kA, cudaFuncAttributeMaxDynamicSharedMemorySize, dynA);

    kA<<<GRID_A, 512, dynA>>>(x, space_w);

    dim3 gB(T_NEED, NB);
    kB<<<gB, 256>>>(temporal_w, last_w);

    kC<<<NB, 64>>>(ama_create, ama_kern, ama_kern_b, ama_alpha,
                   gang_create, gang_kern, gang_kern_b, gang_col, out);
}

// round 4
// speedup vs baseline: 1.3705x; 1.0616x over previous
#include <cuda_runtime.h>
#include <math.h>
#include <stdint.h>

#define NB 16
#define D_NEED 29      // frames d = 31..59
#define D_OFF 31
#define T_NEED 15      // t = 45..59

#define BANDS 2320          // NB * D_NEED * 5 double-bands
#define GRID_A 148          // 1 block per SM
#define STAGES 4
#define BAND_FLOATS 12500   // 50 rows * 250 cols
#define BAND_BYTES 50000

// scratch (no allocations allowed)
__device__ float g_s1[NB * D_NEED * 2500];     // spatial-conv output, 50x50 per (b,d)
__device__ float g_flat[NB * T_NEED * 100];    // last-conv output, 100 per (b,t)

__device__ __forceinline__ unsigned su32(const void* p) {
    return (unsigned)__cvta_generic_to_shared(p);
}

__device__ __forceinline__ void mbar_wait(unsigned mbar, unsigned phase) {
    unsigned done = 0;
    do {
        asm volatile(
            "{\n\t.reg .pred p;\n\t"
            "mbarrier.try_wait.parity.shared.b64 p, [%1], %2, 10000000;\n\t"
            "selp.b32 %0, 1, 0, p;\n\t}"
            : "=r"(done) : "r"(mbar), "r"(phase) : "memory");
    } while (!done);
}

// ---------------------------------------------------------------------------
// Kernel A: 5x5 stride-5 spatial conv on frames 31..59, 4-deep TMA pipeline.
// grid = 148 (1/SM), block = 512, dyn smem = 200 KB (4 x 50 KB band buffers).
// Band id -> (b = id/145, dIdx = (id%145)/5, g2 = id%5): 10 output rows.
// ---------------------------------------------------------------------------
__global__ void __launch_bounds__(512, 1) kA(const float* __restrict__ x,
                                             const float* __restrict__ sw)
{
    extern __shared__ float dbuf[];                 // STAGES * 12500 floats
    __shared__ unsigned long long mbar[STAGES];
    __shared__ float w[25];
    const int tid = threadIdx.x;

    unsigned mb[STAGES], bb[STAGES];
    #pragma unroll
    for (int s = 0; s < STAGES; s++) {
        mb[s] = su32(&mbar[s]);
        bb[s] = su32(dbuf + s * BAND_FLOATS);
    }

    if (tid == 0) {
        #pragma unroll
        for (int s = 0; s < STAGES; s++)
            asm volatile("mbarrier.init.shared.b64 [%0], 1;" :: "r"(mb[s]) : "memory");
        asm volatile("fence.proxy.async.shared::cta;" ::: "memory");
    }
    if (tid < 25) w[tid] = sw[tid];
    __syncthreads();

    const int nMine = (BANDS - 1 - (int)blockIdx.x) / GRID_A + 1;

    auto issueTMA = [&](int j) {
        const int id  = blockIdx.x + j * GRID_A;
        const int b   = id / 145;
        const int rem = id % 145;
        const float* src = x + (size_t)(b * 60 + D_OFF + rem / 5) * 62500u
                             + (size_t)(rem % 5) * BAND_FLOATS;
        const int s = j & (STAGES - 1);
        asm volatile("mbarrier.arrive.expect_tx.shared.b64 _, [%0], %1;"
                     :: "r"(mb[s]), "n"(BAND_BYTES) : "memory");
        asm volatile("cp.async.bulk.shared::cta.global.mbarrier::complete_tx::bytes "
                     "[%0], [%1], %2, [%3];"
                     :: "r"(bb[s]), "l"(src), "n"(BAND_BYTES), "r"(mb[s]) : "memory");
    };

    if (tid == 0) {
        #pragma unroll
        for (int s = 0; s < STAGES - 1; s++)
            if (s < nMine) issueTMA(s);
    }

    for (int j = 0; j < nMine; j++) {
        const int s = j & (STAGES - 1);
        mbar_wait(mb[s], (j >> 2) & 1);

        const int id = blockIdx.x + j * GRID_A;
        if (tid < 500) {
            const float* p = dbuf + s * BAND_FLOATS
                           + (tid / 50) * 1250 + (tid % 50) * 5;
            float acc = 0.f;
            #pragma unroll
            for (int i = 0; i < 5; i++)
                #pragma unroll
                for (int jj = 0; jj < 5; jj++)
                    acc = fmaf(w[i * 5 + jj], p[i * 250 + jj], acc);
            g_s1[id * 500 + tid] = acc;
        }
        __syncthreads();                 // all reads of buffer s done
        if (tid == 0 && j + STAGES - 1 < nMine) issueTMA(j + STAGES - 1);
    }
}

// ---------------------------------------------------------------------------
// Kernel B: temporal 15-tap conv + ReLU + 5x5/stride-5 last conv.
// grid = (10 row-groups, 16 batches), block = 256. Reads g_s1 exactly once.
// Threads 0-249: one pixel column each; load 29 temporal values to regs,
// produce 15 relu'd outputs into smem. Threads 0-149: one (t, outcol) each.
// ---------------------------------------------------------------------------
__global__ void __launch_bounds__(256) kB(const float* __restrict__ tw_g,
                                          const float* __restrict__ lw_g)
{
    __shared__ float sfirst[T_NEED * 250];   // [t][5 rows x 50 cols]
    __shared__ float tw[15];
    __shared__ float lw[25];
    const int grp = blockIdx.x;   // output row h = grp, pixels grp*250..+249
    const int b   = blockIdx.y;
    const int tid = threadIdx.x;

    if (tid < 15) tw[tid] = tw_g[tid];
    if (tid >= 32 && tid < 57) lw[tid - 32] = lw_g[tid - 32];
    __syncthreads();

    if (tid < 250) {
        const float* src = g_s1 + (size_t)b * (D_NEED * 2500) + grp * 250 + tid;
        float v[D_NEED];
        #pragma unroll
        for (int d = 0; d < D_NEED; d++) v[d] = src[d * 2500];
        #pragma unroll
        for (int t = 0; t < T_NEED; t++) {
            float acc = 0.f;
            #pragma unroll
            for (int k = 0; k < 15; k++)
                acc = fmaf(tw[k], v[t + k], acc);
            sfirst[t * 250 + tid] = fmaxf(acc, 0.f);
        }
    }
    __syncthreads();

    if (tid < 150) {
        const int t = tid / 10, c = tid % 10;
        const float* p = sfirst + t * 250 + c * 5;
        float acc = 0.f;
        #pragma unroll
        for (int i = 0; i < 5; i++)
            #pragma unroll
            for (int j = 0; j < 5; j++)
                acc = fmaf(lw[i * 5 + j], p[i * 50 + j], acc);
        g_flat[(b * T_NEED + t) * 100 + grp * 10 + c] = acc;
    }
}

// ---------------------------------------------------------------------------
// Kernel C: ama/gang cone at t=59 + 49-tap dot product. grid = 16, block = 64.
// ---------------------------------------------------------------------------
__global__ void __launch_bounds__(64) kC(const float* __restrict__ acw,
                                         const float* __restrict__ akw,
                                         const float* __restrict__ akb,
                                         const float* __restrict__ alw,
                                         const float* __restrict__ gcw,
                                         const float* __restrict__ gkw,
                                         const float* __restrict__ gkb,
                                         const float* __restrict__ gcolw,
                                         float* __restrict__ out)
{
    __shared__ float fl[T_NEED * 100];
    __shared__ float red[49];
    const int b   = blockIdx.x;
    const int tid = threadIdx.x;

    for (int i = tid; i < T_NEED * 100; i += 64)
        fl[i] = g_flat[b * (T_NEED * 100) + i];
    __syncthreads();

    if (tid < 49) {
        const float ac = acw[0], al = alw[0], gc = gcw[0];
        const int ja = 2 * tid;
        const int jg = (2 * tid + 25) % 100;
        float a = akb[0];
        float g = gkb[0];
        #pragma unroll
        for (int k = 0; k < 15; k++) {
            a = fmaf(akw[k], ac * fl[k * 100 + ja], a);
            g = fmaf(gkw[k], gc * fl[k * 100 + jg], g);
        }
        const float amo = al / (1.f + expf(-a));
        const float val = 1.f / (1.f + expf(-(g - fabsf(amo))));
        red[tid] = gcolw[tid] * val;
    }
    __syncthreads();

    if (tid == 0) {
        float s = 0.f;
        #pragma unroll
        for (int j = 0; j < 49; j++) s += red[j];
        out[b] = s;
    }
}

// ---------------------------------------------------------------------------
extern "C" void kernel_launch(void* const* d_in, const int* in_sizes, int n_in,
                              void* d_out, int out_size)
{
    const float* x          = (const float*)d_in[0];
    const float* space_w    = (const float*)d_in[1];
    const float* temporal_w = (const float*)d_in[2];
    const float* last_w     = (const float*)d_in[3];
    const float* ama_create = (const float*)d_in[4];
    const float* ama_kern   = (const float*)d_in[5];
    const float* ama_kern_b = (const float*)d_in[6];
    const float* ama_alpha  = (const float*)d_in[7];
    const float* gang_create= (const float*)d_in[8];
    const float* gang_kern  = (const float*)d_in[9];
    const float* gang_kern_b= (const float*)d_in[10];
    const float* gang_col   = (const float*)d_in[11];
    float* out = (float*)d_out;

    const int dynA = STAGES * BAND_BYTES;   // 200000 bytes
    cudaFuncSetAttribute(kA, cudaFuncAttributeMaxDynamicSharedMemorySize, dynA);

    kA<<<GRID_A, 512, dynA>>>(x, space_w);

    dim3 gB(10, NB);
    kB<<<gB, 256>>>(temporal_w, last_w);

    kC<<<NB, 64>>>(ama_create, ama_kern, ama_kern_b, ama_alpha,
                   gang_create, gang_kern, gang_kern_b, gang_col, out);
}

// round 6
// speedup vs baseline: 1.3839x; 1.0097x over previous
#include <cuda_runtime.h>
#include <math.h>
#include <stdint.h>

#define NB 16
#define D_NEED 29      // frames d = 31..59
#define D_OFF 31
#define T_NEED 15      // t = 45..59

#define BANDS 11600         // NB * D_NEED * 25 bands (10 input rows each)
#define GRID_A 296          // 2 blocks per SM
#define STAGES 8
#define BAND_FLOATS 2500    // 10 rows * 250 cols
#define BAND_BYTES 10000    // multiple of 16

// scratch (no allocations allowed)
__device__ float g_s1[NB * D_NEED * 2500];     // spatial-conv output, 50x50 per (b,d)
__device__ float g_flat[NB * T_NEED * 100];    // last-conv output, 100 per (b,t)

__device__ __forceinline__ unsigned su32(const void* p) {
    return (unsigned)__cvta_generic_to_shared(p);
}

__device__ __forceinline__ void mbar_wait(unsigned mbar, unsigned phase) {
    unsigned done = 0;
    do {
        asm volatile(
            "{\n\t.reg .pred p;\n\t"
            "mbarrier.try_wait.parity.shared.b64 p, [%1], %2, 10000000;\n\t"
            "selp.b32 %0, 1, 0, p;\n\t}"
            : "=r"(done) : "r"(mbar), "r"(phase) : "memory");
    } while (!done);
}

// ---------------------------------------------------------------------------
// Kernel A: 5x5 stride-5 spatial conv on frames 31..59.
// 296 blocks (2/SM), 128 threads, 8-stage x 10 KB TMA pipeline (80 KB smem).
// Band id -> b = id/725, dIdx = (id%725)/25, g = id%25 : 2 output rows.
// TMA for band j+7 is issued at the TOP of iteration j (its buffer was freed
// by iteration j-1's syncthreads), before waiting on band j.
// ---------------------------------------------------------------------------
__global__ void __launch_bounds__(128) kA(const float* __restrict__ x,
                                          const float* __restrict__ sw)
{
    extern __shared__ float dbuf[];                 // STAGES * 2500 floats
    __shared__ unsigned long long mbar[STAGES];
    __shared__ float w[25];
    const int tid = threadIdx.x;

    unsigned mb[STAGES], bb[STAGES];
    #pragma unroll
    for (int s = 0; s < STAGES; s++) {
        mb[s] = su32(&mbar[s]);
        bb[s] = su32(dbuf + s * BAND_FLOATS);
    }

    if (tid == 0) {
        #pragma unroll
        for (int s = 0; s < STAGES; s++)
            asm volatile("mbarrier.init.shared.b64 [%0], 1;" :: "r"(mb[s]) : "memory");
        asm volatile("fence.proxy.async.shared::cta;" ::: "memory");
    }
    if (tid < 25) w[tid] = sw[tid];
    __syncthreads();

    const int nMine = (BANDS - 1 - (int)blockIdx.x) / GRID_A + 1;

    auto issueTMA = [&](int j) {
        const int id  = blockIdx.x + j * GRID_A;
        const int b   = id / 725;
        const int rem = id % 725;
        const float* src = x + (size_t)(b * 60 + D_OFF + rem / 25) * 62500u
                             + (size_t)(rem % 25) * BAND_FLOATS;
        const int s = j & (STAGES - 1);
        asm volatile("mbarrier.arrive.expect_tx.shared.b64 _, [%0], %1;"
                     :: "r"(mb[s]), "n"(BAND_BYTES) : "memory");
        asm volatile("cp.async.bulk.shared::cta.global.mbarrier::complete_tx::bytes "
                     "[%0], [%1], %2, [%3];"
                     :: "r"(bb[s]), "l"(src), "n"(BAND_BYTES), "r"(mb[s]) : "memory");
    };

    if (tid == 0) {
        #pragma unroll
        for (int s = 0; s < STAGES - 1; s++)
            if (s < nMine) issueTMA(s);
    }

    for (int j = 0; j < nMine; j++) {
        // issue band j+7 first: its buffer was freed by iteration j-1's sync
        if (tid == 0 && j + STAGES - 1 < nMine) issueTMA(j + STAGES - 1);

        const int s = j & (STAGES - 1);
        mbar_wait(mb[s], (j >> 3) & 1);

        const int id = blockIdx.x + j * GRID_A;
        if (tid < 100) {
            const float* p = dbuf + s * BAND_FLOATS
                           + (tid / 50) * 1250 + (tid % 50) * 5;
            float acc = 0.f;
            #pragma unroll
            for (int i = 0; i < 5; i++)
                #pragma unroll
                for (int jj = 0; jj < 5; jj++)
                    acc = fmaf(w[i * 5 + jj], p[i * 250 + jj], acc);
            g_s1[id * 100 + tid] = acc;
        }
        __syncthreads();                 // all reads of buffer s done
    }
}

// ---------------------------------------------------------------------------
// Kernel B: temporal 15-tap conv + ReLU + 5x5/stride-5 last conv.
// grid = (10 row-groups, 16 batches), block = 256. Reads g_s1 exactly once.
// ---------------------------------------------------------------------------
__global__ void __launch_bounds__(256) kB(const float* __restrict__ tw_g,
                                          const float* __restrict__ lw_g)
{
    __shared__ float sfirst[T_NEED * 250];   // [t][5 rows x 50 cols]
    __shared__ float tw[15];
    __shared__ float lw[25];
    const int grp = blockIdx.x;   // output row h = grp, pixels grp*250..+249
    const int b   = blockIdx.y;
    const int tid = threadIdx.x;

    if (tid < 15) tw[tid] = tw_g[tid];
    if (tid >= 32 && tid < 57) lw[tid - 32] = lw_g[tid - 32];
    __syncthreads();

    if (tid < 250) {
        const float* src = g_s1 + (size_t)b * (D_NEED * 2500) + grp * 250 + tid;
        float v[D_NEED];
        #pragma unroll
        for (int d = 0; d < D_NEED; d++) v[d] = src[d * 2500];
        #pragma unroll
        for (int t = 0; t < T_NEED; t++) {
            float acc = 0.f;
            #pragma unroll
            for (int k = 0; k < 15; k++)
                acc = fmaf(tw[k], v[t + k], acc);
            sfirst[t * 250 + tid] = fmaxf(acc, 0.f);
        }
    }
    __syncthreads();

    if (tid < 150) {
        const int t = tid / 10, c = tid % 10;
        const float* p = sfirst + t * 250 + c * 5;
        float acc = 0.f;
        #pragma unroll
        for (int i = 0; i < 5; i++)
            #pragma unroll
            for (int j = 0; j < 5; j++)
                acc = fmaf(lw[i * 5 + j], p[i * 50 + j], acc);
        g_flat[(b * T_NEED + t) * 100 + grp * 10 + c] = acc;
    }
}

// ---------------------------------------------------------------------------
// Kernel C: ama/gang cone at t=59 + 49-tap dot product. grid = 16, block = 64.
// ---------------------------------------------------------------------------
__global__ void __launch_bounds__(64) kC(const float* __restrict__ acw,
                                         const float* __restrict__ akw,
                                         const float* __restrict__ akb,
                                         const float* __restrict__ alw,
                                         const float* __restrict__ gcw,
                                         const float* __restrict__ gkw,
                                         const float* __restrict__ gkb,
                                         const float* __restrict__ gcolw,
                                         float* __restrict__ out)
{
    __shared__ float fl[T_NEED * 100];
    __shared__ float red[49];
    const int b   = blockIdx.x;
    const int tid = threadIdx.x;

    for (int i = tid; i < T_NEED * 100; i += 64)
        fl[i] = g_flat[b * (T_NEED * 100) + i];
    __syncthreads();

    if (tid < 49) {
        const float ac = acw[0], al = alw[0], gc = gcw[0];
        const int ja = 2 * tid;
        const int jg = (2 * tid + 25) % 100;
        float a = akb[0];
        float g = gkb[0];
        #pragma unroll
        for (int k = 0; k < 15; k++) {
            a = fmaf(akw[k], ac * fl[k * 100 + ja], a);
            g = fmaf(gkw[k], gc * fl[k * 100 + jg], g);
        }
        const float amo = al / (1.f + expf(-a));
        const float val = 1.f / (1.f + expf(-(g - fabsf(amo))));
        red[tid] = gcolw[tid] * val;
    }
    __syncthreads();

    if (tid == 0) {
        float s = 0.f;
        #pragma unroll
        for (int j = 0; j < 49; j++) s += red[j];
        out[b] = s;
    }
}

// ---------------------------------------------------------------------------
extern "C" void kernel_launch(void* const* d_in, const int* in_sizes, int n_in,
                              void* d_out, int out_size)
{
    const float* x          = (const float*)d_in[0];
    const float* space_w    = (const float*)d_in[1];
    const float* temporal_w = (const float*)d_in[2];
    const float* last_w     = (const float*)d_in[3];
    const float* ama_create = (const float*)d_in[4];
    const float* ama_kern   = (const float*)d_in[5];
    const float* ama_kern_b = (const float*)d_in[6];
    const float* ama_alpha  = (const float*)d_in[7];
    const float* gang_create= (const float*)d_in[8];
    const float* gang_kern  = (const float*)d_in[9];
    const float* gang_kern_b= (const float*)d_in[10];
    const float* gang_col   = (const float*)d_in[11];
    float* out = (float*)d_out;

    const int dynA = STAGES * BAND_BYTES;   // 80000 bytes
    cudaFuncSetAttribute(kA, cudaFuncAttributeMaxDynamicSharedMemorySize, dynA);

    kA<<<GRID_A, 128, dynA>>>(x, space_w);

    dim3 gB(10, NB);
    kB<<<gB, 256>>>(temporal_w, last_w);

    kC<<<NB, 64>>>(ama_create, ama_kern, ama_kern_b, ama_alpha,
                   gang_create, gang_kern, gang_kern_b, gang_col, out);
}